// round 5
// baseline (speedup 1.0000x reference)
#include <cuda_runtime.h>
#include <cuda_bf16.h>

// PointPWC loss, B=1, N=8192.
// total = 0.02*chamfer + 0.006*curv + 0.01*smooth
//
// R4 (re-run; previous attempt hit a container infra failure):
//  - pairs launch has 3 z-slices (was 4): the pc2-candidate scans (pc2 self-knn
//    and warp->pc2 knn) are fused into one scan with two per-thread top-10 lists.
//  - partial scratch transposed to candidate-major [(slice,chunk,t)][i] so both
//    producer writes and consumer merge reads are fully coalesced.

#define MAXN   8192
#define CHUNKS 8
#define KNN    10
#define TPB    128

// result slices: r=0 pc2-self, r=1 pc1-self, r=2 warp->pc2
#define RSL    3

__device__ float4 g_pc1[MAXN];
__device__ float4 g_pc2[MAXN];
__device__ float4 g_warp[MAXN];
__device__ float4 g_flow[MAXN];
__device__ float4 g_c2[MAXN];
__device__ float4 g_moved[MAXN];
// transposed partials: index = ((r*CHUNKS + c)*KNN + t)*MAXN + i
__device__ float  g_pd[RSL * CHUNKS * KNN * MAXN];
__device__ int    g_pi[RSL * CHUNKS * KNN * MAXN];
__device__ float  g_pmin[CHUNKS * MAXN];          // [c][i]
__device__ double g_acc[4];  // 0: chamfer fwd, 1: chamfer bwd, 2: smooth, 3: curv

__device__ __forceinline__ double warp_red(double v) {
    #pragma unroll
    for (int o = 16; o > 0; o >>= 1)
        v += __shfl_down_sync(0xffffffffu, v, o);
    return v;
}

__global__ void prep_kernel(const float* __restrict__ pred,
                            const float* __restrict__ gt,
                            const float* __restrict__ coords, int n) {
    int i = blockIdx.x * blockDim.x + threadIdx.x;
    if (i == 0) { g_acc[0] = 0.0; g_acc[1] = 0.0; g_acc[2] = 0.0; g_acc[3] = 0.0; }
    if (i >= n) return;
    float cx = coords[3 * i + 0], cy = coords[3 * i + 1], cz = coords[3 * i + 2];
    float gx = gt[3 * i + 0],     gy = gt[3 * i + 1],     gz = gt[3 * i + 2];
    float fx = pred[3 * i + 0],   fy = pred[3 * i + 1],   fz = pred[3 * i + 2];
    float p2x = cx + gx, p2y = cy + gy, p2z = cz + gz;
    float wx  = cx + fx, wy  = cy + fy, wz  = cz + fz;
    g_pc1[i]  = make_float4(cx, cy, cz, cx * cx + cy * cy + cz * cz);
    g_pc2[i]  = make_float4(p2x, p2y, p2z, p2x * p2x + p2y * p2y + p2z * p2z);
    g_warp[i] = make_float4(wx, wy, wz, wx * wx + wy * wy + wz * wz);
    g_flow[i] = make_float4(fx, fy, fz, 0.f);
}

#define INSERT_SORTED(dm, jidx, d, id, kth)                                   \
    do {                                                                      \
        d[KNN - 1] = (dm); id[KNN - 1] = (jidx);                              \
        _Pragma("unroll")                                                     \
        for (int s = KNN - 1; s > 0; --s) {                                   \
            if (d[s] < d[s - 1]) {                                            \
                float td = d[s]; d[s] = d[s - 1]; d[s - 1] = td;              \
                int   ti = id[s]; id[s] = id[s - 1]; id[s - 1] = ti;          \
            }                                                                 \
        }                                                                     \
        kth = d[KNN - 1];                                                     \
    } while (0)

// grid = (n/TPB, CHUNKS, 3)
//  z=0: candidates pc2; dual query (pc2[i] -> r=0, warp[i] -> r=2)
//  z=1: candidates pc1; query pc1[i] -> r=1
//  z=2: candidates warp; query pc2[i] -> reverse-chamfer min
// Distances tracked as dm = |p|^2 - 2<q,p>; true dist = dm + |q|^2 (per-query
// constant shift -> ordering unchanged; ties keep earliest j via strict '<').
__global__ void __launch_bounds__(TPB) pairs_kernel(int n) {
    __shared__ float4 sp[TPB];
    const int slice = blockIdx.z;
    const int i = blockIdx.x * TPB + threadIdx.x;
    const int chunk = n / CHUNKS;
    const int j0 = blockIdx.y * chunk;
    const int ii = (i < n) ? i : 0;

    if (slice == 0) {
        float4 q0 = g_pc2[ii];
        float4 q1 = g_warp[ii];
        float d0[KNN]; int id0[KNN]; float d1[KNN]; int id1[KNN];
        #pragma unroll
        for (int t = 0; t < KNN; t++) {
            d0[t] = 3.4e38f; id0[t] = 0; d1[t] = 3.4e38f; id1[t] = 0;
        }
        float kth0 = 3.4e38f, kth1 = 3.4e38f;
        for (int jb = j0; jb < j0 + chunk; jb += TPB) {
            __syncthreads();
            sp[threadIdx.x] = g_pc2[jb + threadIdx.x];
            __syncthreads();
            #pragma unroll 8
            for (int t = 0; t < TPB; t++) {
                float4 p = sp[t];
                float dot0 = fmaf(q0.x, p.x, fmaf(q0.y, p.y, q0.z * p.z));
                float dot1 = fmaf(q1.x, p.x, fmaf(q1.y, p.y, q1.z * p.z));
                float dm0  = fmaf(-2.f, dot0, p.w);
                float dm1  = fmaf(-2.f, dot1, p.w);
                if (dm0 < kth0) INSERT_SORTED(dm0, jb + t, d0, id0, kth0);
                if (dm1 < kth1) INSERT_SORTED(dm1, jb + t, d1, id1, kth1);
            }
        }
        if (i < n) {
            int b0 = ((0 * CHUNKS + blockIdx.y) * KNN) * MAXN + i;
            int b2 = ((2 * CHUNKS + blockIdx.y) * KNN) * MAXN + i;
            #pragma unroll
            for (int t = 0; t < KNN; t++) {
                g_pd[b0 + t * MAXN] = d0[t] + q0.w; g_pi[b0 + t * MAXN] = id0[t];
                g_pd[b2 + t * MAXN] = d1[t] + q1.w; g_pi[b2 + t * MAXN] = id1[t];
            }
        }
    } else if (slice == 1) {
        float4 q = g_pc1[ii];
        float d[KNN]; int id[KNN];
        #pragma unroll
        for (int t = 0; t < KNN; t++) { d[t] = 3.4e38f; id[t] = 0; }
        float kth = 3.4e38f;
        for (int jb = j0; jb < j0 + chunk; jb += TPB) {
            __syncthreads();
            sp[threadIdx.x] = g_pc1[jb + threadIdx.x];
            __syncthreads();
            #pragma unroll 8
            for (int t = 0; t < TPB; t++) {
                float4 p = sp[t];
                float dot = fmaf(q.x, p.x, fmaf(q.y, p.y, q.z * p.z));
                float dm  = fmaf(-2.f, dot, p.w);
                if (dm < kth) INSERT_SORTED(dm, jb + t, d, id, kth);
            }
        }
        if (i < n) {
            int b1 = ((1 * CHUNKS + blockIdx.y) * KNN) * MAXN + i;
            #pragma unroll
            for (int t = 0; t < KNN; t++) {
                g_pd[b1 + t * MAXN] = d[t] + q.w; g_pi[b1 + t * MAXN] = id[t];
            }
        }
    } else {
        float4 q = g_pc2[ii];
        float m = 3.4e38f;
        for (int jb = j0; jb < j0 + chunk; jb += TPB) {
            __syncthreads();
            sp[threadIdx.x] = g_warp[jb + threadIdx.x];
            __syncthreads();
            #pragma unroll 8
            for (int t = 0; t < TPB; t++) {
                float4 p = sp[t];
                float dot = fmaf(q.x, p.x, fmaf(q.y, p.y, q.z * p.z));
                float dm  = fmaf(-2.f, dot, p.w);
                m = fminf(m, dm);
            }
        }
        if (i < n) g_pmin[blockIdx.y * MAXN + i] = m + q.w;
    }
}

// Stable merge of CHUNKS sorted partials (chunk outer, rank inner = globally
// ascending candidate j for equal distances) -> lax.top_k tie order.
// Coalesced: consecutive threads read consecutive i.
__device__ __forceinline__ void merge_topk(int r, int i, float* d, int* id) {
    #pragma unroll
    for (int t = 0; t < KNN; t++) { d[t] = 3.4e38f; id[t] = 0; }
    #pragma unroll
    for (int c = 0; c < CHUNKS; c++) {
        int base = ((r * CHUNKS + c) * KNN) * MAXN + i;
        #pragma unroll
        for (int t = 0; t < KNN; t++) {
            float dist = g_pd[base + t * MAXN];
            int j = g_pi[base + t * MAXN];
            if (dist < d[KNN - 1]) {
                d[KNN - 1] = dist; id[KNN - 1] = j;
                #pragma unroll
                for (int s = KNN - 1; s > 0; --s) {
                    if (d[s] < d[s - 1]) {
                        float td = d[s]; d[s] = d[s - 1]; d[s - 1] = td;
                        int   ti = id[s]; id[s] = id[s - 1]; id[s - 1] = ti;
                    }
                }
            }
        }
    }
}

// Fused consume: grid.y selects task.
//   y=0: pc2 self-knn -> curvature of pc2
//   y=1: pc1 self-knn -> moved curvature + smoothness accumulation
//   y=2: reverse chamfer min-reduce + accumulation
__global__ void consumeA_kernel(int n, const int* __restrict__ kptr) {
    int i = blockIdx.x * blockDim.x + threadIdx.x;
    int task = blockIdx.y;
    if (task == 0) {
        if (i >= n) return;
        float d[KNN]; int id[KNN];
        merge_topk(0, i, d, id);
        float sx = 0.f, sy = 0.f, sz = 0.f;
        #pragma unroll
        for (int t = 0; t < KNN; t++) {
            float4 p = g_pc2[id[t]];
            sx += p.x; sy += p.y; sz += p.z;
        }
        float4 c = g_pc2[i];
        g_c2[i] = make_float4((sx - 10.f * c.x) / 9.f,
                              (sy - 10.f * c.y) / 9.f,
                              (sz - 10.f * c.z) / 9.f, 0.f);
    } else if (task == 1) {
        double sm_d = 0.0;
        if (i < n) {
            float d[KNN]; int id[KNN];
            merge_topk(1, i, d, id);
            float4 w = g_warp[i];
            float sx = 0.f, sy = 0.f, sz = 0.f;
            #pragma unroll
            for (int t = 0; t < KNN; t++) {
                float4 p = g_warp[id[t]];
                sx += p.x; sy += p.y; sz += p.z;
            }
            g_moved[i] = make_float4((sx - 10.f * w.x) / 9.f,
                                     (sy - 10.f * w.y) / 9.f,
                                     (sz - 10.f * w.z) / 9.f, 0.f);
            int k = *kptr;
            float4 f = g_flow[i];
            float sm = 0.f;
            #pragma unroll
            for (int t = 0; t < KNN; t++) {
                if (t < k) {
                    float4 gfl = g_flow[id[t]];
                    float dx = gfl.x - f.x, dy = gfl.y - f.y, dz = gfl.z - f.z;
                    float sq = dx * dx + dy * dy + dz * dz;
                    sm += sqrtf(sq);   // sq==0 (self) -> 0, matches safe-norm
                }
            }
            sm_d = (double)(sm / 8.f);
        }
        double v = warp_red(sm_d);
        if ((threadIdx.x & 31) == 0) atomicAdd(&g_acc[2], v);
    } else {
        double v = 0.0;
        if (i < n) {
            float m = g_pmin[i];
            #pragma unroll
            for (int c = 1; c < CHUNKS; c++) m = fminf(m, g_pmin[c * MAXN + i]);
            v = (double)m;
        }
        double s = warp_red(v);
        if ((threadIdx.x & 31) == 0) atomicAdd(&g_acc[1], s);
    }
}

// warp->pc2 knn -> chamfer fwd + interpolated-curvature loss
__global__ void cross_consume_kernel(int n) {
    int i = blockIdx.x * blockDim.x + threadIdx.x;
    double d1 = 0.0, cv = 0.0;
    if (i < n) {
        float d[KNN]; int id[KNN];
        merge_topk(2, i, d, id);
        d1 = (double)d[0];
        float w[5]; float wsum = 0.f;
        #pragma unroll
        for (int t = 0; t < 5; t++) { w[t] = 1.f / (d[t] + 1e-8f); wsum += w[t]; }
        float ix = 0.f, iy = 0.f, iz = 0.f;
        #pragma unroll
        for (int t = 0; t < 5; t++) {
            float wn = w[t] / wsum;
            float4 c = g_c2[id[t]];
            ix = fmaf(wn, c.x, ix);
            iy = fmaf(wn, c.y, iy);
            iz = fmaf(wn, c.z, iz);
        }
        float4 m = g_moved[i];
        float ex = ix - m.x, ey = iy - m.y, ez = iz - m.z;
        cv = (double)(ex * ex + ey * ey + ez * ez);
    }
    double v0 = warp_red(d1);
    double v1 = warp_red(cv);
    if ((threadIdx.x & 31) == 0) {
        atomicAdd(&g_acc[0], v0);
        atomicAdd(&g_acc[3], v1);
    }
}

__global__ void finalize_kernel(float* __restrict__ out) {
    if (threadIdx.x == 0) {
        double chamfer = g_acc[0] + g_acc[1];
        double total = 0.02 * chamfer      // F_CHAMFER * ALPHA0
                     + 0.006 * g_acc[3]    // F_CURVATURE * ALPHA0
                     + 0.01  * g_acc[2];   // F_SMOOTH * ALPHA0
        out[0] = (float)total;
    }
}

extern "C" void kernel_launch(void* const* d_in, const int* in_sizes, int n_in,
                              void* d_out, int out_size) {
    const float* pred   = (const float*)d_in[0];  // registration_pred (1,N,3)
    const float* gt     = (const float*)d_in[1];  // registration_gt   (1,N,3)
    const float* coords = (const float*)d_in[2];  // coords            (N,3)
    const int*   kptr   = (const int*)d_in[3];    // smoothness_k

    int n = in_sizes[2] / 3;   // 8192
    int cb = (n + 255) / 256;

    prep_kernel<<<cb, 256>>>(pred, gt, coords, n);
    pairs_kernel<<<dim3(n / TPB, CHUNKS, 3), TPB>>>(n);
    consumeA_kernel<<<dim3(cb, 3), 256>>>(n, kptr);
    cross_consume_kernel<<<cb, 256>>>(n);
    finalize_kernel<<<1, 32>>>((float*)d_out);
}

// round 7
// speedup vs baseline: 1.0112x; 1.0112x over previous
#include <cuda_runtime.h>
#include <cuda_bf16.h>

// PointPWC loss, B=1, N=8192.
// total = 0.02*chamfer + 0.006*curv + 0.01*smooth
//
// R6 (re-run; previous attempt hit a container infra failure):
//  - pairs: 3 z-slices (pc2-candidate scan fused: pc2 self-knn + warp->pc2 knn
//    share one candidate stream with two per-thread top-10 lists).
//  - partial scratch is i-major (per-thread contiguous): the consume merge is a
//    sequential per-thread scan at ~2 warps/SM occupancy, so per-thread cache
//    locality wins over cross-thread coalescing (R5 lesson).
//  - CHUNKS=4: merge scans 40 elements (~2 cache lines/thread).

#define MAXN   8192
#define CHUNKS 4
#define KNN    10
#define TPB    128

// result slices: r=0 pc2-self, r=1 pc1-self, r=2 warp->pc2
#define RSL    3

__device__ float4 g_pc1[MAXN];
__device__ float4 g_pc2[MAXN];
__device__ float4 g_warp[MAXN];
__device__ float4 g_flow[MAXN];
__device__ float4 g_c2[MAXN];
__device__ float4 g_moved[MAXN];
// i-major partials: index = ((r*MAXN + i)*CHUNKS + c)*KNN + t
__device__ float  g_pd[RSL * MAXN * CHUNKS * KNN];
__device__ int    g_pi[RSL * MAXN * CHUNKS * KNN];
__device__ float  g_pmin[MAXN * CHUNKS];          // [i][c]
__device__ double g_acc[4];  // 0: chamfer fwd, 1: chamfer bwd, 2: smooth, 3: curv

__device__ __forceinline__ double warp_red(double v) {
    #pragma unroll
    for (int o = 16; o > 0; o >>= 1)
        v += __shfl_down_sync(0xffffffffu, v, o);
    return v;
}

__global__ void prep_kernel(const float* __restrict__ pred,
                            const float* __restrict__ gt,
                            const float* __restrict__ coords, int n) {
    int i = blockIdx.x * blockDim.x + threadIdx.x;
    if (i == 0) { g_acc[0] = 0.0; g_acc[1] = 0.0; g_acc[2] = 0.0; g_acc[3] = 0.0; }
    if (i >= n) return;
    float cx = coords[3 * i + 0], cy = coords[3 * i + 1], cz = coords[3 * i + 2];
    float gx = gt[3 * i + 0],     gy = gt[3 * i + 1],     gz = gt[3 * i + 2];
    float fx = pred[3 * i + 0],   fy = pred[3 * i + 1],   fz = pred[3 * i + 2];
    float p2x = cx + gx, p2y = cy + gy, p2z = cz + gz;
    float wx  = cx + fx, wy  = cy + fy, wz  = cz + fz;
    g_pc1[i]  = make_float4(cx, cy, cz, cx * cx + cy * cy + cz * cz);
    g_pc2[i]  = make_float4(p2x, p2y, p2z, p2x * p2x + p2y * p2y + p2z * p2z);
    g_warp[i] = make_float4(wx, wy, wz, wx * wx + wy * wy + wz * wz);
    g_flow[i] = make_float4(fx, fy, fz, 0.f);
}

#define INSERT_SORTED(dm, jidx, d, id, kth)                                   \
    do {                                                                      \
        d[KNN - 1] = (dm); id[KNN - 1] = (jidx);                              \
        _Pragma("unroll")                                                     \
        for (int s = KNN - 1; s > 0; --s) {                                   \
            if (d[s] < d[s - 1]) {                                            \
                float td = d[s]; d[s] = d[s - 1]; d[s - 1] = td;              \
                int   ti = id[s]; id[s] = id[s - 1]; id[s - 1] = ti;          \
            }                                                                 \
        }                                                                     \
        kth = d[KNN - 1];                                                     \
    } while (0)

// grid = (n/TPB, CHUNKS, 3)
//  z=0: candidates pc2; dual query (pc2[i] -> r=0, warp[i] -> r=2)
//  z=1: candidates pc1; query pc1[i] -> r=1
//  z=2: candidates warp; query pc2[i] -> reverse-chamfer min
// Distances tracked as dm = |p|^2 - 2<q,p>; true dist = dm + |q|^2 (per-query
// constant shift -> ordering unchanged; ties keep earliest j via strict '<').
__global__ void __launch_bounds__(TPB) pairs_kernel(int n) {
    __shared__ float4 sp[TPB];
    const int slice = blockIdx.z;
    const int i = blockIdx.x * TPB + threadIdx.x;
    const int chunk = n / CHUNKS;
    const int j0 = blockIdx.y * chunk;
    const int ii = (i < n) ? i : 0;

    if (slice == 0) {
        float4 q0 = g_pc2[ii];
        float4 q1 = g_warp[ii];
        float d0[KNN]; int id0[KNN]; float d1[KNN]; int id1[KNN];
        #pragma unroll
        for (int t = 0; t < KNN; t++) {
            d0[t] = 3.4e38f; id0[t] = 0; d1[t] = 3.4e38f; id1[t] = 0;
        }
        float kth0 = 3.4e38f, kth1 = 3.4e38f;
        for (int jb = j0; jb < j0 + chunk; jb += TPB) {
            __syncthreads();
            sp[threadIdx.x] = g_pc2[jb + threadIdx.x];
            __syncthreads();
            #pragma unroll 8
            for (int t = 0; t < TPB; t++) {
                float4 p = sp[t];
                float dot0 = fmaf(q0.x, p.x, fmaf(q0.y, p.y, q0.z * p.z));
                float dot1 = fmaf(q1.x, p.x, fmaf(q1.y, p.y, q1.z * p.z));
                float dm0  = fmaf(-2.f, dot0, p.w);
                float dm1  = fmaf(-2.f, dot1, p.w);
                if (dm0 < kth0) INSERT_SORTED(dm0, jb + t, d0, id0, kth0);
                if (dm1 < kth1) INSERT_SORTED(dm1, jb + t, d1, id1, kth1);
            }
        }
        if (i < n) {
            int b0 = ((0 * MAXN + i) * CHUNKS + blockIdx.y) * KNN;
            int b2 = ((2 * MAXN + i) * CHUNKS + blockIdx.y) * KNN;
            #pragma unroll
            for (int t = 0; t < KNN; t++) {
                g_pd[b0 + t] = d0[t] + q0.w; g_pi[b0 + t] = id0[t];
                g_pd[b2 + t] = d1[t] + q1.w; g_pi[b2 + t] = id1[t];
            }
        }
    } else if (slice == 1) {
        float4 q = g_pc1[ii];
        float d[KNN]; int id[KNN];
        #pragma unroll
        for (int t = 0; t < KNN; t++) { d[t] = 3.4e38f; id[t] = 0; }
        float kth = 3.4e38f;
        for (int jb = j0; jb < j0 + chunk; jb += TPB) {
            __syncthreads();
            sp[threadIdx.x] = g_pc1[jb + threadIdx.x];
            __syncthreads();
            #pragma unroll 8
            for (int t = 0; t < TPB; t++) {
                float4 p = sp[t];
                float dot = fmaf(q.x, p.x, fmaf(q.y, p.y, q.z * p.z));
                float dm  = fmaf(-2.f, dot, p.w);
                if (dm < kth) INSERT_SORTED(dm, jb + t, d, id, kth);
            }
        }
        if (i < n) {
            int b1 = ((1 * MAXN + i) * CHUNKS + blockIdx.y) * KNN;
            #pragma unroll
            for (int t = 0; t < KNN; t++) {
                g_pd[b1 + t] = d[t] + q.w; g_pi[b1 + t] = id[t];
            }
        }
    } else {
        float4 q = g_pc2[ii];
        float m = 3.4e38f;
        for (int jb = j0; jb < j0 + chunk; jb += TPB) {
            __syncthreads();
            sp[threadIdx.x] = g_warp[jb + threadIdx.x];
            __syncthreads();
            #pragma unroll 8
            for (int t = 0; t < TPB; t++) {
                float4 p = sp[t];
                float dot = fmaf(q.x, p.x, fmaf(q.y, p.y, q.z * p.z));
                float dm  = fmaf(-2.f, dot, p.w);
                m = fminf(m, dm);
            }
        }
        if (i < n) g_pmin[i * CHUNKS + blockIdx.y] = m + q.w;
    }
}

// Stable merge of CHUNKS sorted partials (chunk outer, rank inner = globally
// ascending candidate j for equal distances) -> lax.top_k tie order.
// Per-thread contiguous: 40 floats + 40 ints (~2 lines each) -> L1-resident.
__device__ __forceinline__ void merge_topk(int r, int i, float* d, int* id) {
    #pragma unroll
    for (int t = 0; t < KNN; t++) { d[t] = 3.4e38f; id[t] = 0; }
    int base = (r * MAXN + i) * CHUNKS * KNN;
    for (int t = 0; t < CHUNKS * KNN; t++) {
        float dist = g_pd[base + t];
        int j = g_pi[base + t];
        if (dist < d[KNN - 1]) {
            d[KNN - 1] = dist; id[KNN - 1] = j;
            #pragma unroll
            for (int s = KNN - 1; s > 0; --s) {
                if (d[s] < d[s - 1]) {
                    float td = d[s]; d[s] = d[s - 1]; d[s - 1] = td;
                    int   ti = id[s]; id[s] = id[s - 1]; id[s - 1] = ti;
                }
            }
        }
    }
}

// Fused consume: grid.y selects task.
//   y=0: pc2 self-knn -> curvature of pc2
//   y=1: pc1 self-knn -> moved curvature + smoothness accumulation
//   y=2: reverse chamfer min-reduce + accumulation
__global__ void consumeA_kernel(int n, const int* __restrict__ kptr) {
    int i = blockIdx.x * blockDim.x + threadIdx.x;
    int task = blockIdx.y;
    if (task == 0) {
        if (i >= n) return;
        float d[KNN]; int id[KNN];
        merge_topk(0, i, d, id);
        float sx = 0.f, sy = 0.f, sz = 0.f;
        #pragma unroll
        for (int t = 0; t < KNN; t++) {
            float4 p = g_pc2[id[t]];
            sx += p.x; sy += p.y; sz += p.z;
        }
        float4 c = g_pc2[i];
        g_c2[i] = make_float4((sx - 10.f * c.x) / 9.f,
                              (sy - 10.f * c.y) / 9.f,
                              (sz - 10.f * c.z) / 9.f, 0.f);
    } else if (task == 1) {
        double sm_d = 0.0;
        if (i < n) {
            float d[KNN]; int id[KNN];
            merge_topk(1, i, d, id);
            float4 w = g_warp[i];
            float sx = 0.f, sy = 0.f, sz = 0.f;
            #pragma unroll
            for (int t = 0; t < KNN; t++) {
                float4 p = g_warp[id[t]];
                sx += p.x; sy += p.y; sz += p.z;
            }
            g_moved[i] = make_float4((sx - 10.f * w.x) / 9.f,
                                     (sy - 10.f * w.y) / 9.f,
                                     (sz - 10.f * w.z) / 9.f, 0.f);
            int k = *kptr;
            float4 f = g_flow[i];
            float sm = 0.f;
            #pragma unroll
            for (int t = 0; t < KNN; t++) {
                if (t < k) {
                    float4 gfl = g_flow[id[t]];
                    float dx = gfl.x - f.x, dy = gfl.y - f.y, dz = gfl.z - f.z;
                    float sq = dx * dx + dy * dy + dz * dz;
                    sm += sqrtf(sq);   // sq==0 (self) -> 0, matches safe-norm
                }
            }
            sm_d = (double)(sm / 8.f);
        }
        double v = warp_red(sm_d);
        if ((threadIdx.x & 31) == 0) atomicAdd(&g_acc[2], v);
    } else {
        double v = 0.0;
        if (i < n) {
            float m = g_pmin[i * CHUNKS];
            #pragma unroll
            for (int c = 1; c < CHUNKS; c++) m = fminf(m, g_pmin[i * CHUNKS + c]);
            v = (double)m;
        }
        double s = warp_red(v);
        if ((threadIdx.x & 31) == 0) atomicAdd(&g_acc[1], s);
    }
}

// warp->pc2 knn -> chamfer fwd + interpolated-curvature loss
__global__ void cross_consume_kernel(int n) {
    int i = blockIdx.x * blockDim.x + threadIdx.x;
    double d1 = 0.0, cv = 0.0;
    if (i < n) {
        float d[KNN]; int id[KNN];
        merge_topk(2, i, d, id);
        d1 = (double)d[0];
        float w[5]; float wsum = 0.f;
        #pragma unroll
        for (int t = 0; t < 5; t++) { w[t] = 1.f / (d[t] + 1e-8f); wsum += w[t]; }
        float ix = 0.f, iy = 0.f, iz = 0.f;
        #pragma unroll
        for (int t = 0; t < 5; t++) {
            float wn = w[t] / wsum;
            float4 c = g_c2[id[t]];
            ix = fmaf(wn, c.x, ix);
            iy = fmaf(wn, c.y, iy);
            iz = fmaf(wn, c.z, iz);
        }
        float4 m = g_moved[i];
        float ex = ix - m.x, ey = iy - m.y, ez = iz - m.z;
        cv = (double)(ex * ex + ey * ey + ez * ez);
    }
    double v0 = warp_red(d1);
    double v1 = warp_red(cv);
    if ((threadIdx.x & 31) == 0) {
        atomicAdd(&g_acc[0], v0);
        atomicAdd(&g_acc[3], v1);
    }
}

__global__ void finalize_kernel(float* __restrict__ out) {
    if (threadIdx.x == 0) {
        double chamfer = g_acc[0] + g_acc[1];
        double total = 0.02 * chamfer      // F_CHAMFER * ALPHA0
                     + 0.006 * g_acc[3]    // F_CURVATURE * ALPHA0
                     + 0.01  * g_acc[2];   // F_SMOOTH * ALPHA0
        out[0] = (float)total;
    }
}

extern "C" void kernel_launch(void* const* d_in, const int* in_sizes, int n_in,
                              void* d_out, int out_size) {
    const float* pred   = (const float*)d_in[0];  // registration_pred (1,N,3)
    const float* gt     = (const float*)d_in[1];  // registration_gt   (1,N,3)
    const float* coords = (const float*)d_in[2];  // coords            (N,3)
    const int*   kptr   = (const int*)d_in[3];    // smoothness_k

    int n = in_sizes[2] / 3;   // 8192
    int cb = (n + 255) / 256;

    prep_kernel<<<cb, 256>>>(pred, gt, coords, n);
    pairs_kernel<<<dim3(n / TPB, CHUNKS, 3), TPB>>>(n);
    consumeA_kernel<<<dim3(cb, 3), 256>>>(n, kptr);
    cross_consume_kernel<<<cb, 256>>>(n);
    finalize_kernel<<<1, 32>>>((float*)d_out);
}

// round 9
// speedup vs baseline: 1.5351x; 1.5181x over previous
#include <cuda_runtime.h>
#include <cuda_bf16.h>

// PointPWC loss, B=1, N=8192.
// total = 0.02*chamfer + 0.006*curv + 0.01*smooth
//
// R7 (re-run; previous attempt hit a container infra failure):
//  Insert-cost-centric redesign of the O(N^2) pass.
//  Cost model (from R1 profile): the sorted-insert chain under warp divergence
//  dominates (~45 instr executed whenever ANY lane inserts ~ min(1,32K/j)).
//  So: CHUNKS=2 (fewer fresh-list transients), TPB=256 (occupancy), 4
//  independent single-list slices (no dual lists), and the cross slice keeps
//  only top-5 (all its consumers need: top-5 interp + min chamfer).
//  Scratch stays i-major (R5 lesson: per-thread locality >> coalescing for the
//  low-occupancy sequential merge).

#define MAXN   8192
#define CHUNKS 2
#define KNN    10
#define KNN5   5
#define TPB    256

__device__ float4 g_pc1[MAXN];
__device__ float4 g_pc2[MAXN];
__device__ float4 g_warp[MAXN];
__device__ float4 g_flow[MAXN];
__device__ float4 g_c2[MAXN];
__device__ float4 g_moved[MAXN];
// i-major partials: index = ((r*MAXN + i)*CHUNKS + c)*K + t   (K=10 slots even for r=2)
__device__ float  g_pd[3 * MAXN * CHUNKS * KNN];
__device__ int    g_pi[3 * MAXN * CHUNKS * KNN];
__device__ float  g_pmin[MAXN * CHUNKS];          // [i][c]
__device__ double g_acc[4];  // 0: chamfer fwd, 1: chamfer bwd, 2: smooth, 3: curv

__device__ __forceinline__ double warp_red(double v) {
    #pragma unroll
    for (int o = 16; o > 0; o >>= 1)
        v += __shfl_down_sync(0xffffffffu, v, o);
    return v;
}

__global__ void prep_kernel(const float* __restrict__ pred,
                            const float* __restrict__ gt,
                            const float* __restrict__ coords, int n) {
    int i = blockIdx.x * blockDim.x + threadIdx.x;
    if (i == 0) { g_acc[0] = 0.0; g_acc[1] = 0.0; g_acc[2] = 0.0; g_acc[3] = 0.0; }
    if (i >= n) return;
    float cx = coords[3 * i + 0], cy = coords[3 * i + 1], cz = coords[3 * i + 2];
    float gx = gt[3 * i + 0],     gy = gt[3 * i + 1],     gz = gt[3 * i + 2];
    float fx = pred[3 * i + 0],   fy = pred[3 * i + 1],   fz = pred[3 * i + 2];
    float p2x = cx + gx, p2y = cy + gy, p2z = cz + gz;
    float wx  = cx + fx, wy  = cy + fy, wz  = cz + fz;
    g_pc1[i]  = make_float4(cx, cy, cz, cx * cx + cy * cy + cz * cz);
    g_pc2[i]  = make_float4(p2x, p2y, p2z, p2x * p2x + p2y * p2y + p2z * p2z);
    g_warp[i] = make_float4(wx, wy, wz, wx * wx + wy * wy + wz * wz);
    g_flow[i] = make_float4(fx, fy, fz, 0.f);
}

template <int K>
__device__ __forceinline__ void insert_sorted(float dm, int j,
                                              float (&d)[K], int (&id)[K],
                                              float& kth) {
    d[K - 1] = dm; id[K - 1] = j;
    #pragma unroll
    for (int s = K - 1; s > 0; --s) {
        if (d[s] < d[s - 1]) {
            float td = d[s]; d[s] = d[s - 1]; d[s - 1] = td;
            int   ti = id[s]; id[s] = id[s - 1]; id[s - 1] = ti;
        }
    }
    kth = d[K - 1];
}

// Block-cooperative scan of candidates [j0, j0+chunk) from P, maintaining a
// per-thread sorted top-K of dm = |p|^2 - 2<q,p> (true dist = dm + |q|^2;
// constant per-query shift keeps ordering; strict '<' keeps earliest j on ties).
template <int K>
__device__ __forceinline__ void knn_scan(const float4* __restrict__ P,
                                         float4 q, int j0, int chunk,
                                         float4* sp,
                                         float (&d)[K], int (&id)[K]) {
    #pragma unroll
    for (int t = 0; t < K; t++) { d[t] = 3.4e38f; id[t] = 0; }
    float kth = 3.4e38f;
    for (int jb = j0; jb < j0 + chunk; jb += TPB) {
        __syncthreads();
        sp[threadIdx.x] = P[jb + threadIdx.x];
        __syncthreads();
        #pragma unroll 8
        for (int t = 0; t < TPB; t++) {
            float4 p = sp[t];
            float dot = fmaf(q.x, p.x, fmaf(q.y, p.y, q.z * p.z));
            float dm  = fmaf(-2.f, dot, p.w);
            if (dm < kth) insert_sorted<K>(dm, jb + t, d, id, kth);
        }
    }
}

// grid = (n/TPB, CHUNKS, 4)
//  z=0: pc2 self-knn (K=10) -> r=0
//  z=1: pc1 self-knn (K=10) -> r=1
//  z=2: warp -> pc2 (K=5)   -> r=2
//  z=3: pc2 -> warp min (reverse chamfer)
__global__ void __launch_bounds__(TPB) pairs_kernel(int n) {
    __shared__ float4 sp[TPB];
    const int slice = blockIdx.z;
    const int i = blockIdx.x * TPB + threadIdx.x;
    const int chunk = n / CHUNKS;
    const int j0 = blockIdx.y * chunk;
    const int ii = (i < n) ? i : 0;

    if (slice == 0) {
        float4 q = g_pc2[ii];
        float d[KNN]; int id[KNN];
        knn_scan<KNN>(g_pc2, q, j0, chunk, sp, d, id);
        if (i < n) {
            int b = ((0 * MAXN + i) * CHUNKS + blockIdx.y) * KNN;
            #pragma unroll
            for (int t = 0; t < KNN; t++) { g_pd[b + t] = d[t] + q.w; g_pi[b + t] = id[t]; }
        }
    } else if (slice == 1) {
        float4 q = g_pc1[ii];
        float d[KNN]; int id[KNN];
        knn_scan<KNN>(g_pc1, q, j0, chunk, sp, d, id);
        if (i < n) {
            int b = ((1 * MAXN + i) * CHUNKS + blockIdx.y) * KNN;
            #pragma unroll
            for (int t = 0; t < KNN; t++) { g_pd[b + t] = d[t] + q.w; g_pi[b + t] = id[t]; }
        }
    } else if (slice == 2) {
        float4 q = g_warp[ii];
        float d[KNN5]; int id[KNN5];
        knn_scan<KNN5>(g_pc2, q, j0, chunk, sp, d, id);
        if (i < n) {
            int b = ((2 * MAXN + i) * CHUNKS + blockIdx.y) * KNN;
            #pragma unroll
            for (int t = 0; t < KNN5; t++) { g_pd[b + t] = d[t] + q.w; g_pi[b + t] = id[t]; }
        }
    } else {
        float4 q = g_pc2[ii];
        float m = 3.4e38f;
        for (int jb = j0; jb < j0 + chunk; jb += TPB) {
            __syncthreads();
            sp[threadIdx.x] = g_warp[jb + threadIdx.x];
            __syncthreads();
            #pragma unroll 8
            for (int t = 0; t < TPB; t++) {
                float4 p = sp[t];
                float dot = fmaf(q.x, p.x, fmaf(q.y, p.y, q.z * p.z));
                float dm  = fmaf(-2.f, dot, p.w);
                m = fminf(m, dm);
            }
        }
        if (i < n) g_pmin[i * CHUNKS + blockIdx.y] = m + q.w;
    }
}

// Stable merge of CHUNKS sorted partials (chunk outer, rank inner = globally
// ascending candidate j for equal distances) -> lax.top_k tie order.
// Per-thread contiguous scratch -> L1 resident after first miss.
template <int K>
__device__ __forceinline__ void merge_topk(int r, int i, float (&d)[K], int (&id)[K]) {
    #pragma unroll
    for (int t = 0; t < K; t++) { d[t] = 3.4e38f; id[t] = 0; }
    int base = (r * MAXN + i) * CHUNKS * KNN;
    #pragma unroll
    for (int c = 0; c < CHUNKS; c++) {
        #pragma unroll
        for (int t = 0; t < K; t++) {
            float dist = g_pd[base + c * KNN + t];
            int j = g_pi[base + c * KNN + t];
            if (dist < d[K - 1]) {
                d[K - 1] = dist; id[K - 1] = j;
                #pragma unroll
                for (int s = K - 1; s > 0; --s) {
                    if (d[s] < d[s - 1]) {
                        float td = d[s]; d[s] = d[s - 1]; d[s - 1] = td;
                        int   ti = id[s]; id[s] = id[s - 1]; id[s - 1] = ti;
                    }
                }
            }
        }
    }
}

// Fused consume: grid.y selects task.
//   y=0: pc2 self-knn -> curvature of pc2
//   y=1: pc1 self-knn -> moved curvature + smoothness accumulation
//   y=2: reverse chamfer min-reduce + accumulation
__global__ void consumeA_kernel(int n, const int* __restrict__ kptr) {
    int i = blockIdx.x * blockDim.x + threadIdx.x;
    int task = blockIdx.y;
    if (task == 0) {
        if (i >= n) return;
        float d[KNN]; int id[KNN];
        merge_topk<KNN>(0, i, d, id);
        float sx = 0.f, sy = 0.f, sz = 0.f;
        #pragma unroll
        for (int t = 0; t < KNN; t++) {
            float4 p = g_pc2[id[t]];
            sx += p.x; sy += p.y; sz += p.z;
        }
        float4 c = g_pc2[i];
        g_c2[i] = make_float4((sx - 10.f * c.x) / 9.f,
                              (sy - 10.f * c.y) / 9.f,
                              (sz - 10.f * c.z) / 9.f, 0.f);
    } else if (task == 1) {
        double sm_d = 0.0;
        if (i < n) {
            float d[KNN]; int id[KNN];
            merge_topk<KNN>(1, i, d, id);
            float4 w = g_warp[i];
            float sx = 0.f, sy = 0.f, sz = 0.f;
            #pragma unroll
            for (int t = 0; t < KNN; t++) {
                float4 p = g_warp[id[t]];
                sx += p.x; sy += p.y; sz += p.z;
            }
            g_moved[i] = make_float4((sx - 10.f * w.x) / 9.f,
                                     (sy - 10.f * w.y) / 9.f,
                                     (sz - 10.f * w.z) / 9.f, 0.f);
            int k = *kptr;
            float4 f = g_flow[i];
            float sm = 0.f;
            #pragma unroll
            for (int t = 0; t < KNN; t++) {
                if (t < k) {
                    float4 gfl = g_flow[id[t]];
                    float dx = gfl.x - f.x, dy = gfl.y - f.y, dz = gfl.z - f.z;
                    float sq = dx * dx + dy * dy + dz * dz;
                    sm += sqrtf(sq);   // sq==0 (self) -> 0, matches safe-norm
                }
            }
            sm_d = (double)(sm / 8.f);
        }
        double v = warp_red(sm_d);
        if ((threadIdx.x & 31) == 0) atomicAdd(&g_acc[2], v);
    } else {
        double v = 0.0;
        if (i < n) {
            float m = g_pmin[i * CHUNKS];
            #pragma unroll
            for (int c = 1; c < CHUNKS; c++) m = fminf(m, g_pmin[i * CHUNKS + c]);
            v = (double)m;
        }
        double s = warp_red(v);
        if ((threadIdx.x & 31) == 0) atomicAdd(&g_acc[1], s);
    }
}

// warp->pc2 top-5 -> chamfer fwd + interpolated-curvature loss
__global__ void cross_consume_kernel(int n) {
    int i = blockIdx.x * blockDim.x + threadIdx.x;
    double d1 = 0.0, cv = 0.0;
    if (i < n) {
        float d[KNN5]; int id[KNN5];
        merge_topk<KNN5>(2, i, d, id);
        d1 = (double)d[0];
        float w[5]; float wsum = 0.f;
        #pragma unroll
        for (int t = 0; t < 5; t++) { w[t] = 1.f / (d[t] + 1e-8f); wsum += w[t]; }
        float ix = 0.f, iy = 0.f, iz = 0.f;
        #pragma unroll
        for (int t = 0; t < 5; t++) {
            float wn = w[t] / wsum;
            float4 c = g_c2[id[t]];
            ix = fmaf(wn, c.x, ix);
            iy = fmaf(wn, c.y, iy);
            iz = fmaf(wn, c.z, iz);
        }
        float4 m = g_moved[i];
        float ex = ix - m.x, ey = iy - m.y, ez = iz - m.z;
        cv = (double)(ex * ex + ey * ey + ez * ez);
    }
    double v0 = warp_red(d1);
    double v1 = warp_red(cv);
    if ((threadIdx.x & 31) == 0) {
        atomicAdd(&g_acc[0], v0);
        atomicAdd(&g_acc[3], v1);
    }
}

__global__ void finalize_kernel(float* __restrict__ out) {
    if (threadIdx.x == 0) {
        double chamfer = g_acc[0] + g_acc[1];
        double total = 0.02 * chamfer      // F_CHAMFER * ALPHA0
                     + 0.006 * g_acc[3]    // F_CURVATURE * ALPHA0
                     + 0.01  * g_acc[2];   // F_SMOOTH * ALPHA0
        out[0] = (float)total;
    }
}

extern "C" void kernel_launch(void* const* d_in, const int* in_sizes, int n_in,
                              void* d_out, int out_size) {
    const float* pred   = (const float*)d_in[0];  // registration_pred (1,N,3)
    const float* gt     = (const float*)d_in[1];  // registration_gt   (1,N,3)
    const float* coords = (const float*)d_in[2];  // coords            (N,3)
    const int*   kptr   = (const int*)d_in[3];    // smoothness_k

    int n = in_sizes[2] / 3;   // 8192
    int cb = (n + 255) / 256;

    prep_kernel<<<cb, 256>>>(pred, gt, coords, n);
    pairs_kernel<<<dim3(n / TPB, CHUNKS, 4), TPB>>>(n);
    consumeA_kernel<<<dim3(cb, 3), 256>>>(n, kptr);
    cross_consume_kernel<<<cb, 256>>>(n);
    finalize_kernel<<<1, 32>>>((float*)d_out);
}